// round 16
// baseline (speedup 1.0000x reference)
#include <cuda_runtime.h>
#include <cstdint>

typedef unsigned long long ull;

#define BATCH 16
#define HH 128
#define WW 128
#define LANES 64          // 128 channels = 64 ull lanes
#define TROWS 16          // output rows per block
#define TCOLS 16          // output cols per block
#define RING 4            // per-warp ring slots
#define WSEG_BYTES (6 * 32 * 8)          // 1536 B: one row segment (6 cols x 32 lanes)
#define WSLOT_STRIDE WSEG_BYTES
#define WRING_BYTES (RING * WSEG_BYTES)  // 6144 B per warp
#define THREADS 256

// ---- packed fp32x2 primitives (sm_103a) ----
__device__ __forceinline__ ull mulp(ull a, ull b) {
    ull r; asm("mul.rn.f32x2 %0, %1, %2;" : "=l"(r) : "l"(a), "l"(b)); return r;
}
__device__ __forceinline__ ull addp(ull a, ull b) {
    ull r; asm("add.rn.f32x2 %0, %1, %2;" : "=l"(r) : "l"(a), "l"(b)); return r;
}
__device__ __forceinline__ ull fmap(ull a, ull b, ull c) {
    ull r; asm("fma.rn.f32x2 %0, %1, %2, %3;" : "=l"(r) : "l"(a), "l"(b), "l"(c)); return r;
}
__device__ __forceinline__ ull pack2f(float x) {
    ull r; asm("mov.b64 %0, {%1, %1};" : "=l"(r) : "f"(x)); return r;
}
__device__ __forceinline__ ull absp(ull u) { return u & 0x7FFFFFFF7FFFFFFFULL; }
__device__ __forceinline__ void stcs8(ull* p, ull v) {
    asm volatile("st.global.cs.b64 [%0], %1;" :: "l"(p), "l"(v) : "memory");
}

// ---- cp.async helpers (per-thread group state -> warp-autonomous pipeline) ----
__device__ __forceinline__ void cp16(uint32_t saddr, const void* g) {
    asm volatile("cp.async.ca.shared.global [%0], [%1], 16;" :: "r"(saddr), "l"(g));
}
__device__ __forceinline__ void cp_commit() {
    asm volatile("cp.async.commit_group;" ::: "memory");
}
template <int N> __device__ __forceinline__ void cp_wait() {
    asm volatile("cp.async.wait_group %0;" :: "n"(N) : "memory");
}
__device__ __forceinline__ ull lds8(uint32_t a) {
    ull v; asm volatile("ld.shared.b64 %0, [%1];" : "=l"(v) : "r"(a)); return v;
}

// block = 256 threads = 8 warps. warp w: cg = w>>1 (4 output cols), half = w&1
// (which 32-of-64 ull channel lanes). Each warp owns a PRIVATE smem ring and
// synchronizes only with __syncwarp — no __syncthreads in the main loop.
// tile: 16 rows x 16 cols x 128 ch; grid = (8, 8, 16) = 1024 blocks
__global__ __launch_bounds__(THREADS, 4)
void act_filter_kernel(const ull* __restrict__ X, ull* __restrict__ O) {
    __shared__ ull ring[8][RING][6][32];   // 49152 B = 48 KB static

    const int tid    = threadIdx.x;
    const int w      = tid >> 5;
    const int lane32 = tid & 31;
    const int cg     = w >> 1;
    const int half   = w & 1;
    const int j0c    = blockIdx.x * TCOLS + cg * 4;
    const int i0     = blockIdx.y * TROWS;
    const int b      = blockIdx.z;

    const ull w25 = pack2f(0.25f);
    const ull w75 = pack2f(0.75f);
    const ull ca  = pack2f(0.12625f);   // 0.505*0.25  (lrelu = 0.505u + 0.495|u|)
    const ull cb  = pack2f(0.12375f);   // 0.495*0.25

    const uint32_t wbase = (uint32_t)__cvta_generic_to_shared(&ring[w][0][0][0]);

    // clamped source columns for this warp's 6 staged slots
    int cl[6];
#pragma unroll
    for (int t = 0; t < 6; t++) {
        int c = j0c - 1 + t;
        cl[t] = (c < 0) ? 0 : ((c > WW - 1) ? WW - 1 : c);
    }

    // per-thread cp chunks: q=0..2, chunk id c = lane32 + 32q (0..95)
    // smem offset within slot = c*16 ; gmem col-byte = cl[c>>4]*512 + half*256 + (c&15)*16
    uint32_t g_colbyte[3];
#pragma unroll
    for (int q = 0; q < 3; q++) {
        const int c = lane32 + 32 * q;
        g_colbyte[q] = (uint32_t)(cl[c >> 4] * (LANES * 8) + half * 256 + (c & 15) * 16);
    }

    const char* __restrict__ gX = (const char*)X;

    // stage input row k (rows i0-1 .. i0+16) into this warp's slot k%RING
    auto issue_row = [&](int k) {
        int rin = i0 - 1 + k;
        rin = (rin < 0) ? 0 : ((rin > HH - 1) ? HH - 1 : rin);
        const size_t rowbyte = (size_t)((b * HH + rin) * WW) * (LANES * 8);
        const uint32_t sbase = wbase + (k % RING) * WSLOT_STRIDE;
#pragma unroll
        for (int q = 0; q < 3; q++)
            cp16(sbase + (lane32 + 32 * q) * 16, gX + rowbyte + g_colbyte[q]);
        cp_commit();
    };

    // prologue: stage rows 0..2
    issue_row(0); issue_row(1); issue_row(2);

    ull* __restrict__ po = O + ((size_t)((b * HH + i0) * WW + j0c)) * LANES
                             + half * 32 + lane32;
    const uint32_t lbyte = lane32 * 8;

    // rotating raw-x window: xw[k%3][t] = input row k, staged col t (registers)
    ull xw[3][6];

    cp_wait<1>();          // rows 0,1 complete ({2} outstanding)
    __syncwarp();
#pragma unroll
    for (int k = 0; k < 2; k++) {
        const uint32_t sbase = wbase + k * WSLOT_STRIDE;
#pragma unroll
        for (int t = 0; t < 6; t++) xw[k][t] = lds8(sbase + t * 256 + lbyte);
    }

#pragma unroll
    for (int r = 0; r < TROWS; r++) {
        // issue row r+3 (slot occupant row r-1: its smem was last read at iter r-3)
        if (r + 3 <= TROWS + 1) { issue_row(r + 3); cp_wait<1>(); }
        else                    { cp_wait<0>(); }
        __syncwarp();          // warp-wide visibility of row r+2

        // load ONLY the new input row (k=r+2) into the register window
        {
            const uint32_t sbase = wbase + ((r + 2) % RING) * WSLOT_STRIDE;
#pragma unroll
            for (int t = 0; t < 6; t++)
                xw[(r + 2) % 3][t] = lds8(sbase + t * 256 + lbyte);
        }

        const ull* xm = xw[r % 3];         // input row i-1
        const ull* x0 = xw[(r + 1) % 3];   // input row i
        const ull* xp = xw[(r + 2) % 3];   // input row i+1

        // vertical mixes (shared 0.75*x0 term)
        ull vp[6], vq[6];
#pragma unroll
        for (int t = 0; t < 6; t++) {
            ull t75 = mulp(x0[t], w75);
            vp[t] = fmap(xm[t], w25, t75);
            vq[t] = fmap(xp[t], w25, t75);
        }

        // horizontal mixes + blend for 4 output cols (shared 0.75*v[t] terms)
#pragma unroll
        for (int jj = 0; jj < 4; jj++) {
            const int t = jj + 1;
            ull hp = mulp(vp[t], w75);
            ull hq = mulp(vq[t], w75);
            ull u00 = fmap(vp[t - 1], w25, hp);
            ull u01 = fmap(vp[t + 1], w25, hp);
            ull u10 = fmap(vq[t - 1], w25, hq);
            ull u11 = fmap(vq[t + 1], w25, hq);
            ull sl = addp(addp(u00, u01), addp(u10, u11));
            ull sa = addp(addp(absp(u00), absp(u01)), addp(absp(u10), absp(u11)));
            stcs8(po + (size_t)r * WW * LANES + jj * LANES,
                  fmap(sl, ca, mulp(sa, cb)));
        }
    }
}

extern "C" void kernel_launch(void* const* d_in, const int* in_sizes, int n_in,
                              void* d_out, int out_size) {
    const ull* X = (const ull*)d_in[0];
    ull* O = (ull*)d_out;
    dim3 block(THREADS, 1, 1);
    dim3 grid(WW / TCOLS, HH / TROWS, BATCH);   // 8, 8, 16
    act_filter_kernel<<<grid, block>>>(X, O);
}

// round 17
// speedup vs baseline: 1.0428x; 1.0428x over previous
#include <cuda_runtime.h>
#include <cstdint>

typedef unsigned long long ull;

#define BATCH 16
#define HH 128
#define WW 128
#define LANES 64          // 128 channels = 64 ull lanes
#define TROWS 16          // output rows per block
#define TCOLS 16          // output cols per block
#define NCOLS 18          // staged cols per row segment (halo included)
#define RING 5            // ring depth (5*18*64*8 = 46080 B static smem)
#define SEG_ULL (NCOLS * LANES)          // 1152 ull per row segment
#define SEG_BYTES (SEG_ULL * 8)          // 9216
#define SEG_CHUNKS (SEG_BYTES / 16)      // 576 x 16B
#define THREADS 256

// ---- packed fp32x2 primitives (sm_103a) ----
__device__ __forceinline__ ull mulp(ull a, ull b) {
    ull r; asm("mul.rn.f32x2 %0, %1, %2;" : "=l"(r) : "l"(a), "l"(b)); return r;
}
__device__ __forceinline__ ull addp(ull a, ull b) {
    ull r; asm("add.rn.f32x2 %0, %1, %2;" : "=l"(r) : "l"(a), "l"(b)); return r;
}
__device__ __forceinline__ ull fmap(ull a, ull b, ull c) {
    ull r; asm("fma.rn.f32x2 %0, %1, %2, %3;" : "=l"(r) : "l"(a), "l"(b), "l"(c)); return r;
}
__device__ __forceinline__ ull pack2f(float x) {
    ull r; asm("mov.b64 %0, {%1, %1};" : "=l"(r) : "f"(x)); return r;
}
__device__ __forceinline__ ull absp(ull u) { return u & 0x7FFFFFFF7FFFFFFFULL; }
__device__ __forceinline__ void stcs8(ull* p, ull v) {
    asm volatile("st.global.cs.b64 [%0], %1;" :: "l"(p), "l"(v) : "memory");
}

// ---- cp.async helpers ----
__device__ __forceinline__ void cp16(uint32_t saddr, const void* g) {
    asm volatile("cp.async.ca.shared.global [%0], [%1], 16;" :: "r"(saddr), "l"(g));
}
__device__ __forceinline__ void cp_commit() {
    asm volatile("cp.async.commit_group;" ::: "memory");
}
template <int N> __device__ __forceinline__ void cp_wait() {
    asm volatile("cp.async.wait_group %0;" :: "n"(N) : "memory");
}
__device__ __forceinline__ ull lds8(uint32_t a) {
    ull v; asm volatile("ld.shared.b64 %0, [%1];" : "=l"(v) : "r"(a)); return v;
}

// block = 256 threads: lane = tid&63 (ull channel), cg = tid>>6 (4 col groups of 4)
// tile: 16 output rows x 16 output cols x 128 ch; grid = (8, 8, 16) = 1024 blocks
// minBlocksPerMultiprocessor=4 caps regs at 64 -> 4 resident blocks/SM
// TWO output rows per __syncthreads (9 barriers/block instead of 17)
__global__ __launch_bounds__(THREADS, 4)
void act_filter_kernel(const ull* __restrict__ X, ull* __restrict__ O) {
    __shared__ ull ring[RING][SEG_ULL];

    const int tid  = threadIdx.x;
    const int lane = tid & (LANES - 1);
    const int cg   = tid >> 6;                  // 0..3
    const int j0   = blockIdx.x * TCOLS;
    const int i0   = blockIdx.y * TROWS;
    const int b    = blockIdx.z;

    // staged column range start (so [cstart, cstart+17] subset of [0,127])
    const int cstart = (j0 == 0) ? 0 : ((j0 == WW - TCOLS) ? (WW - NCOLS) : j0 - 1);

    const ull w25 = pack2f(0.25f);
    const ull w75 = pack2f(0.75f);
    const ull ca  = pack2f(0.12625f);   // 0.505*0.25  (lrelu = 0.505u + 0.495|u|)
    const ull cb  = pack2f(0.12375f);   // 0.495*0.25

    const uint32_t sring = (uint32_t)__cvta_generic_to_shared(&ring[0][0]);

    // producer: stage input row k (k indexes rows i0-1 .. i0+16) into slot k%RING
    auto issue_row = [&](int k) {
        int rin = i0 - 1 + k;
        rin = (rin < 0) ? 0 : ((rin > HH - 1) ? HH - 1 : rin);
        const char* gsrc = (const char*)(X + ((size_t)((b * HH + rin) * WW + cstart)) * LANES);
        const uint32_t sbase = sring + (k % RING) * SEG_BYTES;
#pragma unroll
        for (int c = tid; c < SEG_CHUNKS; c += THREADS)
            cp16(sbase + c * 16, gsrc + (size_t)c * 16);
        cp_commit();
    };

    // prologue: stage rows k = 0..3
    issue_row(0); issue_row(1); issue_row(2); issue_row(3);

    // this thread's 6 clamped source-column byte offsets within a segment
    const int j0c = j0 + cg * 4;
    uint32_t wcb[6];
#pragma unroll
    for (int t = 0; t < 6; t++) {
        int c = j0c - 1 + t;
        c = (c < 0) ? 0 : ((c > WW - 1) ? WW - 1 : c);
        wcb[t] = (uint32_t)(((c - cstart) * LANES + lane) * 8);
    }

    ull* __restrict__ po = O + ((size_t)((b * HH + i0) * WW + j0c)) * LANES + lane;

    // rotating raw-x window: xw[k%3][t] = input row k, source col t
    ull xw[3][6];

    // prime window with rows k=0 (i0-1) and k=1 (i0); rows 0..1 complete
    cp_wait<2>();
    __syncthreads();
#pragma unroll
    for (int k = 0; k < 2; k++) {
        const uint32_t sbase = sring + k * SEG_BYTES;
#pragma unroll
        for (int t = 0; t < 6; t++) xw[k][t] = lds8(sbase + wcb[t]);
    }

#pragma unroll
    for (int r = 0; r < TROWS; r += 2) {
        // pre-barrier issue of row r+4: slot occupant k=r-1, last LDS two barriers ago
        if (r + 4 <= TROWS + 1) { issue_row(r + 4); cp_wait<1>(); }
        else                    { cp_wait<0>(); }
        __syncthreads();                 // rows <= r+3 published block-wide

        // post-barrier issue of row r+5: slot occupant k=r, reads sealed by the
        // barrier above (its LDS happened in pair-iteration r-2)
        if (r + 5 <= TROWS + 1) issue_row(r + 5);

        // ---- two output rows per barrier ----
#pragma unroll
        for (int rr = r; rr < r + 2; rr++) {
            // rotate in the new input row k=rr+2
            {
                const uint32_t sbase = sring + ((rr + 2) % RING) * SEG_BYTES;
#pragma unroll
                for (int t = 0; t < 6; t++)
                    xw[(rr + 2) % 3][t] = lds8(sbase + wcb[t]);
            }

            const ull* xm = xw[rr % 3];         // input row i-1
            const ull* x0 = xw[(rr + 1) % 3];   // input row i
            const ull* xp = xw[(rr + 2) % 3];   // input row i+1

            // vertical mixes (shared 0.75*x0 term)
            ull vp[6], vq[6];
#pragma unroll
            for (int t = 0; t < 6; t++) {
                ull t75 = mulp(x0[t], w75);
                vp[t] = fmap(xm[t], w25, t75);
                vq[t] = fmap(xp[t], w25, t75);
            }

            // horizontal mixes + blend (shared 0.75*v[t] terms)
#pragma unroll
            for (int jj = 0; jj < 4; jj++) {
                const int t = jj + 1;
                ull hp = mulp(vp[t], w75);
                ull hq = mulp(vq[t], w75);
                ull u00 = fmap(vp[t - 1], w25, hp);
                ull u01 = fmap(vp[t + 1], w25, hp);
                ull u10 = fmap(vq[t - 1], w25, hq);
                ull u11 = fmap(vq[t + 1], w25, hq);
                ull sl = addp(addp(u00, u01), addp(u10, u11));
                ull sa = addp(addp(absp(u00), absp(u01)), addp(absp(u10), absp(u11)));
                stcs8(po + (size_t)rr * WW * LANES + jj * LANES,
                      fmap(sl, ca, mulp(sa, cb)));
            }
        }
    }
}

extern "C" void kernel_launch(void* const* d_in, const int* in_sizes, int n_in,
                              void* d_out, int out_size) {
    const ull* X = (const ull*)d_in[0];
    ull* O = (ull*)d_out;
    dim3 block(THREADS, 1, 1);
    dim3 grid(WW / TCOLS, HH / TROWS, BATCH);   // 8, 8, 16
    act_filter_kernel<<<grid, block>>>(X, O);
}